// round 6
// baseline (speedup 1.0000x reference)
#include <cuda_runtime.h>
#include <cuda_bf16.h>

// CapsuleRoutingPooling — reduced form (softmax over singleton axis => c ≡ 1):
//   out[b,c,nh,nw,:] = squash( sum over 2x2 window of inp[b,c,2nh+dh,2nw+dw,:] )
// B=16, C=64, H=W=64, D=16, k=2 -> nH=nW=32. 268 MB read + 67 MB write.
//
// 4 threads per output vector (quad covers contiguous 64B half-lines per
// LDG; stores 512B-coalesced per warp) AND 2 vectors per thread (elements g
// and g + n_half) for 8 independent in-flight LDG.128s -> deeper MLP to close
// the last few % to the HBM ceiling. Quad-local shfl.bfly (xor1, xor2)
// reduces the D=16 squared norm.

#define D_DIM 16

__global__ __launch_bounds__(256, 8)
void capsule_pool_squash_kernel(const float* __restrict__ inp,
                                float* __restrict__ out,
                                int n_half)   // (4 * n_vec) / 2
{
    int g = blockIdx.x * blockDim.x + threadIdx.x;
    if (g >= n_half) return;

    // element 0: g ; element 1: g + n_half
    int p0   = g & 3;
    int idx0 = g >> 2;
    int e1   = g + n_half;
    int p1   = e1 & 3;
    int idx1 = e1 >> 2;

    // decode input bases: idx = ((bc*32)+nh)*32 + nw
    int nw0 = idx0 & 31, t0 = idx0 >> 5, nh0 = t0 & 31, bc0 = t0 >> 5;
    int nw1 = idx1 & 31, t1 = idx1 >> 5, nh1 = t1 & 31, bc1 = t1 >> 5;

    long long base0 = ((long long)(bc0 * 64 + 2 * nh0) * 64 + 2 * nw0) * D_DIM;
    long long base1 = ((long long)(bc1 * 64 + 2 * nh1) * 64 + 2 * nw1) * D_DIM;

    // Window rows: 8 float4 per 128B row (chunks 0..3 = w, 4..7 = w+1).
    // Row stride h->h+1 = W*D = 1024 floats = 256 float4.
    const float4* a0 = reinterpret_cast<const float4*>(inp + base0) + p0;
    const float4* b0 = reinterpret_cast<const float4*>(inp + base1) + p1;

    // issue all 8 loads back-to-back for max MLP
    float4 A0 = __ldcs(a0);
    float4 A1 = __ldcs(a0 + 4);
    float4 A2 = __ldcs(a0 + 256);
    float4 A3 = __ldcs(a0 + 260);
    float4 B0 = __ldcs(b0);
    float4 B1 = __ldcs(b0 + 4);
    float4 B2 = __ldcs(b0 + 256);
    float4 B3 = __ldcs(b0 + 260);

    float4 sa, sb;
    sa.x = (A0.x + A1.x) + (A2.x + A3.x);
    sa.y = (A0.y + A1.y) + (A2.y + A3.y);
    sa.z = (A0.z + A1.z) + (A2.z + A3.z);
    sa.w = (A0.w + A1.w) + (A2.w + A3.w);
    sb.x = (B0.x + B1.x) + (B2.x + B3.x);
    sb.y = (B0.y + B1.y) + (B2.y + B3.y);
    sb.z = (B0.z + B1.z) + (B2.z + B3.z);
    sb.w = (B0.w + B1.w) + (B2.w + B3.w);

    // squared norms over D=16: quad reduction (xor 1, xor 2 stay in the quad)
    float pa = sa.x * sa.x + sa.y * sa.y + sa.z * sa.z + sa.w * sa.w;
    float pb = sb.x * sb.x + sb.y * sb.y + sb.z * sb.z + sb.w * sb.w;
    pa += __shfl_xor_sync(0xFFFFFFFFu, pa, 1);
    pb += __shfl_xor_sync(0xFFFFFFFFu, pb, 1);
    pa += __shfl_xor_sync(0xFFFFFFFFu, pa, 2);
    pb += __shfl_xor_sync(0xFFFFFFFFu, pb, 2);

    float ka = pa / ((1.0f + pa) * (sqrtf(pa) + 1e-8f));
    float kb = pb / ((1.0f + pb) * (sqrtf(pb) + 1e-8f));

    sa.x *= ka; sa.y *= ka; sa.z *= ka; sa.w *= ka;
    sb.x *= kb; sb.y *= kb; sb.z *= kb; sb.w *= kb;

    // fully coalesced stores: quad lanes write 64B contiguous per vector
    float4* ob = reinterpret_cast<float4*>(out);
    __stcs(ob + (long long)idx0 * 4 + p0, sa);
    __stcs(ob + (long long)idx1 * 4 + p1, sb);
}

extern "C" void kernel_launch(void* const* d_in, const int* in_sizes, int n_in,
                              void* d_out, int out_size)
{
    const float* inp = (const float*)d_in[0];
    float* out = (float*)d_out;

    int n_vec  = out_size / D_DIM;   // 1,048,576
    int n_thr  = n_vec * 4;          // 4,194,304
    int n_half = n_thr / 2;          // 2,097,152
    if (n_half <= 0) return;
    int threads = 256;
    int blocks = (n_half + threads - 1) / threads;   // 8192
    capsule_pool_squash_kernel<<<blocks, threads>>>(inp, out, n_half);
}